// round 13
// baseline (speedup 1.0000x reference)
#include <cuda_runtime.h>
#include <cuda_bf16.h>
#include <math_constants.h>
#include <cstdint>
#include <mma.h>

using namespace nvcuda;

#define NB 16
#define LQ 4096          // L
#define DD 512           // D
#define CC 512           // 2*Cin
#define UU 450           // top-k count
#define UP 512           // padded U
#define PER_BATCH (LQ*DD)

typedef __nv_bfloat16 bf16;

// ---------------- device scratch ----------------
__device__ float g_v[(size_t)NB*PER_BATCH];     // proj-V flat [o][4096] == v[l][d]
__device__ float g_S[(size_t)NB*PER_BATCH];     // scores [u][4096] (fp32)
__device__ float g_updA[(size_t)NB*UP*DD];      // upd partial K half 0
__device__ float g_updB[(size_t)NB*UP*DD];      // upd partial K half 1
__device__ int   g_topk[NB*UP];
__device__ int   g_ulookup[NB*LQ];              // l -> u or -1
__device__ float2 g_Mpart[NB*LQ*2];             // qks fused max/sum partials (2 N-tiles)
__device__ float g_smaxp[NB*UP*16];             // scores fused row-max partials (16 N-tiles)
__device__ float g_vpart[NB*16*DD];
__device__ float g_vmean[NB*DD];
__device__ float g_denom[NB*UP];

__device__ __align__(16) bf16 g_Whi[3*DD*CC],            g_Wlo[3*DD*CC];
__device__ __align__(16) bf16 g_XThi[(size_t)NB*LQ*CC],  g_XTlo[(size_t)NB*LQ*CC];  // [s][c]
__device__ __align__(16) bf16 g_Qhi[(size_t)NB*LQ*DD],   g_Qlo[(size_t)NB*LQ*DD];   // flat: [o][4096] == q[l][d]
__device__ __align__(16) bf16 g_Khi[(size_t)NB*LQ*DD],   g_Klo[(size_t)NB*LQ*DD];   // flat
__device__ __align__(16) bf16 g_KShi[(size_t)NB*UP*DD],  g_KSlo[(size_t)NB*UP*DD];  // [s][d]
__device__ __align__(16) bf16 g_QRhi[(size_t)NB*UP*DD],  g_QRlo[(size_t)NB*UP*DD];  // [u][d]
__device__ __align__(16) bf16 g_SEhi[(size_t)NB*UP*LQ],  g_SElo[(size_t)NB*UP*LQ];  // [u][l]
__device__ __align__(16) bf16 g_VThi[(size_t)NB*DD*LQ],  g_VTlo[(size_t)NB*DD*LQ];  // [d][l]

// ---------------- static-init streams/events (pre-checkpoint) ----------------
struct StrHolder {
    cudaStream_t s1;
    cudaEvent_t eFork, eVT, eVM;
    StrHolder() {
        cudaStreamCreateWithFlags(&s1, cudaStreamNonBlocking);
        cudaEventCreateWithFlags(&eFork, cudaEventDisableTiming);
        cudaEventCreateWithFlags(&eVT,   cudaEventDisableTiming);
        cudaEventCreateWithFlags(&eVM,   cudaEventDisableTiming);
    }
};
static StrHolder g_str;

// ---------------- helpers ----------------
__device__ __forceinline__ uint32_t smem_u32(const void* p) {
    uint32_t a;
    asm("{ .reg .u64 t; cvta.to.shared.u64 t, %1; cvt.u32.u64 %0, t; }" : "=r"(a) : "l"(p));
    return a;
}
__device__ __forceinline__ void cpa16(uint32_t dst, const void* src) {
    asm volatile("cp.async.cg.shared.global [%0], [%1], 16;" :: "r"(dst), "l"(src));
}
__device__ __forceinline__ void cp_commit() { asm volatile("cp.async.commit_group;" ::: "memory"); }
template<int N> __device__ __forceinline__ void cp_wait() {
    asm volatile("cp.async.wait_group %0;" :: "n"(N) : "memory");
}
__device__ __forceinline__ bf16 hi_of(float x) { return __float2bfloat16(x); }
__device__ __forceinline__ bf16 lo_of(float x, bf16 h) { return __float2bfloat16(x - __bfloat162float(h)); }

// ============================================================================
// wmma GEMM: CTA tile 128(M) x 256(N), BK=32, 8 warps (2M x 4N), warp 64x64,
// double-buffered cp.async. A [Mtot][lda] K-major hi/lo, B [Ntot][lda] hi/lo.
// NPROD=3: Ah*Bh + Ah*Bl + Al*Bh.  NPROD=2: Ah*Bh + Al*Bh (Blo unloaded).
// EPI: 2 qks: NO C write; masked (col<UU) row max/sum partials -> part(float2)
//      3 scores: alpha fp32 + row-max partials -> part(float)
//      4 plain fp32 (upd partial)
//      5 proj: row-bias; Chi!=null -> bf16 split else fp32
// ============================================================================
#define SA 48                     // smem row stride in halfs (96B)
#define ARR_A (128*SA*2)          // 12288 B
#define ARR_B (256*SA*2)          // 24576 B
#define STAGE (2*ARR_A + 2*ARR_B) // 73728 B
#define SM_TOTAL (2*STAGE)        // 147456 B (C-stage 128*260*4=133120 reuses)

template<int EPI, int NPROD>
__device__ __forceinline__ void gemm_wmma(
    const bf16* __restrict__ Ahi, const bf16* __restrict__ Alo,
    const bf16* __restrict__ Bhi, const bf16* __restrict__ Blo,
    int KEXT, int lda,
    float* __restrict__ C, bf16* __restrict__ Chi, bf16* __restrict__ Clo, int ldc,
    const float* __restrict__ aux, float alpha, float* __restrict__ part)
{
    extern __shared__ char sm[];
    const uint32_t smb = smem_u32(sm);
    const int tid = threadIdx.x, w = tid >> 5;
    const int mw = w >> 2, nw = w & 3;           // 2M x 4N warp grid
    const int m0 = blockIdx.y * 128, n0 = blockIdx.x * 256;
    const int NS = KEXT >> 5;

    wmma::fragment<wmma::accumulator, 16, 16, 16, float> fc[4][4];
    #pragma unroll
    for (int i = 0; i < 4; i++)
        #pragma unroll
        for (int j = 0; j < 4; j++) wmma::fill_fragment(fc[i][j], 0.f);

    auto load_stage = [&](int s, int bufb) {
        const int k0 = s << 5;
        const uint32_t base = smb + bufb * STAGE;
        #pragma unroll
        for (int q = 0; q < 2; q++) {
            const bf16* src = q ? Alo : Ahi;
            const uint32_t dst = base + q * ARR_A;
            #pragma unroll
            for (int c0 = 0; c0 < 512; c0 += 256) {
                int c = c0 + tid;
                int row = c >> 2, col = c & 3;
                cpa16(dst + row * 96 + col * 16,
                      src + (size_t)(m0 + row) * lda + k0 + col * 8);
            }
        }
        #pragma unroll
        for (int q = 0; q < 2; q++) {
            if (NPROD == 2 && q == 1) break;     // skip Blo entirely
            const bf16* src = q ? Blo : Bhi;
            const uint32_t dst = base + 2 * ARR_A + q * ARR_B;
            #pragma unroll
            for (int c0 = 0; c0 < 1024; c0 += 256) {
                int c = c0 + tid;
                int row = c >> 2, col = c & 3;
                cpa16(dst + row * 96 + col * 16,
                      src + (size_t)(n0 + row) * lda + k0 + col * 8);
            }
        }
        cp_commit();
    };

    load_stage(0, 0);

    for (int s = 0; s < NS; s++) {
        const int b = s & 1;
        if (s + 1 < NS) { load_stage(s + 1, b ^ 1); cp_wait<1>(); }
        else            { cp_wait<0>(); }
        __syncthreads();

        const bf16* sAh = (const bf16*)(sm + b * STAGE);
        const bf16* sAl = (const bf16*)(sm + b * STAGE + ARR_A);
        const bf16* sBh = (const bf16*)(sm + b * STAGE + 2 * ARR_A);
        const bf16* sBl = (const bf16*)(sm + b * STAGE + 2 * ARR_A + ARR_B);

        #pragma unroll
        for (int ks = 0; ks < 2; ks++) {
            wmma::fragment<wmma::matrix_a, 16, 16, 16, bf16, wmma::row_major> fah[4], fal[4];
            #pragma unroll
            for (int i = 0; i < 4; i++) {
                const int r = mw * 64 + i * 16;
                wmma::load_matrix_sync(fah[i], sAh + r * SA + ks * 16, SA);
                wmma::load_matrix_sync(fal[i], sAl + r * SA + ks * 16, SA);
            }
            #pragma unroll
            for (int j = 0; j < 4; j++) {
                wmma::fragment<wmma::matrix_b, 16, 16, 16, bf16, wmma::col_major> fbh, fbl;
                const int n = nw * 64 + j * 16;
                wmma::load_matrix_sync(fbh, sBh + n * SA + ks * 16, SA);
                if (NPROD == 3)
                    wmma::load_matrix_sync(fbl, sBl + n * SA + ks * 16, SA);
                // products-outer: same per-accumulator order (hh, hl, lh) ->
                // bit-identical results, but dependent-HMMA distance = 4.
                #pragma unroll
                for (int i = 0; i < 4; i++)
                    wmma::mma_sync(fc[i][j], fah[i], fbh, fc[i][j]);
                if (NPROD == 3) {
                    #pragma unroll
                    for (int i = 0; i < 4; i++)
                        wmma::mma_sync(fc[i][j], fah[i], fbl, fc[i][j]);
                }
                #pragma unroll
                for (int i = 0; i < 4; i++)
                    wmma::mma_sync(fc[i][j], fal[i], fbh, fc[i][j]);
            }
        }
        __syncthreads();
    }

    // ---- epilogue via smem C-stage (known layout), 128 x 260 fp32 ----
    float* csm = (float*)sm;
    #pragma unroll
    for (int i = 0; i < 4; i++)
        #pragma unroll
        for (int j = 0; j < 4; j++)
            wmma::store_matrix_sync(csm + (mw*64 + i*16) * 260 + nw*64 + j*16,
                                    fc[i][j], 260, wmma::mem_row_major);
    __syncthreads();

    const int r = tid >> 1, gm = m0 + r;
    const int cb0 = (tid & 1) * 128;
    const float* src = csm + r * 260 + cb0;

    if (EPI == 5) {                       // proj: row bias; split or fp32
        const float add = aux[gm];
        if (Chi) {
            #pragma unroll
            for (int g = 0; g < 4; g++) {
                ushort hs[32], ls[32];
                #pragma unroll
                for (int c = 0; c < 32; c++) {
                    float v = src[g * 32 + c] + add;
                    bf16 h = hi_of(v);
                    hs[c] = __bfloat16_as_ushort(h);
                    ls[c] = __bfloat16_as_ushort(lo_of(v, h));
                }
                bf16* ph = Chi + (size_t)gm * ldc + n0 + cb0 + g * 32;
                bf16* pl = Clo + (size_t)gm * ldc + n0 + cb0 + g * 32;
                #pragma unroll
                for (int j = 0; j < 4; j++) {
                    *(uint4*)(ph + j * 8) = *(uint4*)&hs[j * 8];
                    *(uint4*)(pl + j * 8) = *(uint4*)&ls[j * 8];
                }
            }
        } else {
            float* pc = C + (size_t)gm * ldc + n0 + cb0;
            #pragma unroll
            for (int j = 0; j < 32; j++) {
                float4 v = *(const float4*)(src + j * 4);
                v.x += add; v.y += add; v.z += add; v.w += add;
                *(float4*)(pc + j * 4) = v;
            }
        }
    } else if (EPI == 2) {                // qks: masked row max/sum, no C write
        float mx = -CUDART_INF_F, smv = 0.f;
        #pragma unroll 8
        for (int c = 0; c < 128; c++) {
            int scol = n0 + cb0 + c;
            if (scol < UU) { float v = src[c]; mx = fmaxf(mx, v); smv += v; }
        }
        float mx2 = fmaxf(mx, __shfl_xor_sync(0xffffffffu, mx, 1));
        float sm2 = smv + __shfl_xor_sync(0xffffffffu, smv, 1);
        if ((tid & 1) == 0)
            ((float2*)part)[gm * 2 + blockIdx.x] = make_float2(mx2, sm2);
    } else {
        float mul = (EPI == 3) ? alpha : 1.f;
        float* pc = C + (size_t)gm * ldc + n0 + cb0;
        float mx = -CUDART_INF_F;
        #pragma unroll
        for (int j = 0; j < 32; j++) {
            float4 v = *(const float4*)(src + j * 4);
            v.x *= mul; v.y *= mul; v.z *= mul; v.w *= mul;
            if (EPI == 3) mx = fmaxf(mx, fmaxf(fmaxf(v.x, v.y), fmaxf(v.z, v.w)));
            *(float4*)(pc + j * 4) = v;
        }
        if (EPI == 3) {
            float mx2 = fmaxf(mx, __shfl_xor_sync(0xffffffffu, mx, 1));
            if ((tid & 1) == 0) part[gm * 16 + blockIdx.x] = mx2;
        }
    }
}

// ---------------- merged proj kernel (Q, K, V in one launch) ----------------
__global__ __launch_bounds__(256, 1) void k_proj(const float* __restrict__ bq,
                                                 const float* __restrict__ bk,
                                                 const float* __restrict__ bv)
{
    int z = blockIdx.z, mi = z >> 4, b = z & 15;
    const float* bias = (mi == 0) ? bq : (mi == 1) ? bk : bv;
    bf16 *Ch = nullptr, *Cl = nullptr;
    float* C = nullptr;
    if (mi == 0)      { Ch = g_Qhi + (size_t)b*PER_BATCH; Cl = g_Qlo + (size_t)b*PER_BATCH; }
    else if (mi == 1) { Ch = g_Khi + (size_t)b*PER_BATCH; Cl = g_Klo + (size_t)b*PER_BATCH; }
    else              { C  = g_v   + (size_t)b*PER_BATCH; }
    gemm_wmma<5, 3>(g_Whi + (size_t)mi*DD*CC, g_Wlo + (size_t)mi*DD*CC,
                    g_XThi + (size_t)b*LQ*CC, g_XTlo + (size_t)b*LQ*CC, CC, CC,
                    C, Ch, Cl, LQ, bias, 1.f, nullptr);
}
// QKs fused: only max/sum partials, no matrix output (3-product: feeds top-k)
__global__ __launch_bounds__(256, 1) void k_qks()
{
    int b = blockIdx.z;
    gemm_wmma<2, 3>(g_Qhi + (size_t)b*PER_BATCH, g_Qlo + (size_t)b*PER_BATCH,
                    g_KShi + (size_t)b*UP*DD, g_KSlo + (size_t)b*UP*DD, DD, DD,
                    nullptr, nullptr, nullptr, UP, nullptr, 1.f,
                    (float*)(g_Mpart + (size_t)b*LQ*2));
}
// scores: 2-product (QR split x K_hi)
__global__ __launch_bounds__(256, 1) void k_scores()
{
    int b = blockIdx.z;
    gemm_wmma<3, 2>(g_QRhi + (size_t)b*UP*DD, g_QRlo + (size_t)b*UP*DD,
                    g_Khi + (size_t)b*PER_BATCH, nullptr, DD, DD,
                    g_S + (size_t)b*PER_BATCH, nullptr, nullptr, LQ, nullptr,
                    0.044194173824159216f, g_smaxp + (size_t)b*UP*16);
}
// upd partial: K split in halves; z = half*16 + b
__global__ __launch_bounds__(256, 1) void k_upd()
{
    int z = blockIdx.z, h = z >> 4, b = z & 15;
    const size_t koff = (size_t)h * 2048;
    float* dst = (h ? g_updB : g_updA) + (size_t)b*UP*DD;
    gemm_wmma<4, 3>(g_SEhi + (size_t)b*UP*LQ + koff, g_SElo + (size_t)b*UP*LQ + koff,
                    g_VThi + (size_t)b*DD*LQ + koff, g_VTlo + (size_t)b*DD*LQ + koff,
                    2048, LQ,
                    dst, nullptr, nullptr, DD, nullptr, 1.f, nullptr);
}

// ---------------- conversions ----------------
__global__ void k_convW(const float* __restrict__ Wq, const float* __restrict__ Wk,
                        const float* __restrict__ Wv)
{
    int i = blockIdx.x * 256 + threadIdx.x;
    int mi = i >> 18, r = i & 262143;
    const float* W = (mi == 0) ? Wq : (mi == 1) ? Wk : Wv;
    float x = W[r];
    bf16 h = hi_of(x);
    g_Whi[i] = h; g_Wlo[i] = lo_of(x, h);
}

__global__ void k_convX(const float* __restrict__ in1, const float* __restrict__ in2)
{
    __shared__ float t[32][33];
    int b = blockIdx.z, s0 = blockIdx.x * 32, c0 = blockIdx.y * 32;
    const float* src = (c0 < 256) ? (in1 + ((size_t)b * 256 + c0) * LQ)
                                  : (in2 + ((size_t)b * 256 + (c0 - 256)) * LQ);
    for (int i = threadIdx.y; i < 32; i += 8)
        t[i][threadIdx.x] = src[(size_t)i * LQ + s0 + threadIdx.x];
    __syncthreads();
    for (int i = threadIdx.y; i < 32; i += 8) {
        float x = t[threadIdx.x][i];
        bf16 h = hi_of(x);
        size_t off = ((size_t)b * LQ + s0 + i) * CC + c0 + threadIdx.x;
        g_XThi[off] = h; g_XTlo[off] = lo_of(x, h);
    }
}

__global__ void k_transV()
{
    __shared__ float t[32][33];
    int b = blockIdx.z, d0 = blockIdx.x * 32, l0 = blockIdx.y * 32;
    const float* src = g_v + (size_t)b * PER_BATCH;
    for (int i = threadIdx.y; i < 32; i += 8)
        t[i][threadIdx.x] = src[(size_t)(l0 + i) * DD + d0 + threadIdx.x];
    __syncthreads();
    for (int i = threadIdx.y; i < 32; i += 8) {
        float x = t[threadIdx.x][i];
        bf16 h = hi_of(x);
        size_t off = ((size_t)b * DD + d0 + i) * LQ + l0 + threadIdx.x;
        g_VThi[off] = h; g_VTlo[off] = lo_of(x, h);
    }
}

// ---------------- gathers ----------------
__global__ void k_gather_ks(const int* __restrict__ idx)
{
    int b = blockIdx.y, s = blockIdx.x, t = threadIdx.x;
    size_t drow = ((size_t)b * UP + s) * DD;
    uint2* dh = (uint2*)(g_KShi + drow);
    uint2* dl = (uint2*)(g_KSlo + drow);
    if (s < UU) {
        size_t srow = ((size_t)b * LQ + idx[s]) * DD;
        dh[t] = ((const uint2*)(g_Khi + srow))[t];
        dl[t] = ((const uint2*)(g_Klo + srow))[t];
    } else {
        dh[t] = make_uint2(0, 0); dl[t] = make_uint2(0, 0);
    }
}
__global__ void k_gather_qr()
{
    int b = blockIdx.y, u = blockIdx.x, t = threadIdx.x;
    size_t drow = ((size_t)b * UP + u) * DD;
    uint2* dh = (uint2*)(g_QRhi + drow);
    uint2* dl = (uint2*)(g_QRlo + drow);
    if (u < UU) {
        size_t srow = ((size_t)b * LQ + g_topk[b * UP + u]) * DD;
        dh[t] = ((const uint2*)(g_Qhi + srow))[t];
        dl[t] = ((const uint2*)(g_Qlo + srow))[t];
    } else {
        dh[t] = make_uint2(0, 0); dl[t] = make_uint2(0, 0);
    }
}

// ---------------- top-k (M from qks partials) + inverse lookup ----------------
__global__ __launch_bounds__(1024) void k_topk()
{
    __shared__ float sv[LQ];
    __shared__ int   si[LQ];
    int b = blockIdx.x;
    for (int i = threadIdx.x; i < LQ; i += 1024) {
        float2 p0 = g_Mpart[(size_t)(b * LQ + i) * 2 + 0];
        float2 p1 = g_Mpart[(size_t)(b * LQ + i) * 2 + 1];
        sv[i] = fmaxf(p0.x, p1.x) - (p0.y + p1.y) * (1.0f / LQ);
        si[i] = i;
        g_ulookup[b * LQ + i] = -1;
    }
    __syncthreads();
    for (int k = 2; k <= LQ; k <<= 1) {
        for (int j = k >> 1; j > 0; j >>= 1) {
            for (int t = threadIdx.x; t < LQ / 2; t += 1024) {
                int i = ((t & ~(j - 1)) << 1) | (t & (j - 1));
                int ixj = i | j;
                bool desc = ((i & k) == 0);
                float a = sv[i], c = sv[ixj];
                bool sw = desc ? (a < c) : (a > c);
                if (sw) { sv[i] = c; sv[ixj] = a; int ti = si[i]; si[i] = si[ixj]; si[ixj] = ti; }
            }
            __syncthreads();
        }
    }
    for (int u = threadIdx.x; u < UU; u += 1024) {
        g_topk[b * UP + u] = si[u];
        g_ulookup[b * LQ + si[u]] = u;
    }
}

// ---------------- softmax (single pass; max from scores partials) ----------------
__global__ __launch_bounds__(256) void k_softmax()
{
    int b = blockIdx.y, u = blockIdx.x, t = threadIdx.x;
    size_t off = (size_t)b * PER_BATCH + (size_t)u * LQ;
    bf16* eh = g_SEhi + off;
    bf16* el = g_SElo + off;
    if (u >= UU) {
        for (int l = t; l < LQ; l += 256) { eh[l] = __ushort_as_bfloat16(0); el[l] = __ushort_as_bfloat16(0); }
        if (t == 0) g_denom[b * UP + u] = 1.f;
        return;
    }
    const float* mp = g_smaxp + ((size_t)b * UP + u) * 16;
    float mx = -CUDART_INF_F;
    #pragma unroll
    for (int i = 0; i < 16; i++) mx = fmaxf(mx, mp[i]);

    const float* row = g_S + off;
    __shared__ float red[256];
    float sm = 0.f;
    for (int l = t; l < LQ; l += 256) {
        float e = expf(row[l] - mx);
        bf16 h = hi_of(e);
        eh[l] = h; el[l] = lo_of(e, h);
        sm += e;
    }
    red[t] = sm; __syncthreads();
    for (int o = 128; o; o >>= 1) { if (t < o) red[t] += red[t + o]; __syncthreads(); }
    if (t == 0) g_denom[b * UP + u] = red[0];
}

// ---------------- V column means ----------------
__global__ void k_vmean1()
{
    int b = blockIdx.y, c = blockIdx.x;
    const float* V = g_v + (size_t)b * PER_BATCH + (size_t)c * 256 * DD;
    int d = threadIdx.x;
    float acc = 0.f;
    #pragma unroll 4
    for (int l = 0; l < 256; l++) acc += V[l * DD + d];
    g_vpart[((size_t)b * 16 + c) * DD + d] = acc;
}
__global__ void k_vmean2()
{
    int b = blockIdx.x, d = threadIdx.x;
    float acc = 0.f;
    #pragma unroll
    for (int c = 0; c < 16; c++) acc += g_vpart[((size_t)b * 16 + c) * DD + d];
    g_vmean[b * DD + d] = acc * (1.0f / LQ);
}

// ---------------- fused output: vmean broadcast or (updA+updB)/denom ----------------
__global__ void k_output(float* __restrict__ out)
{
    int b = blockIdx.y, l = blockIdx.x, t = threadIdx.x;
    int u = g_ulookup[b * LQ + l];
    float4 r;
    if (u >= 0) {
        float inv = 1.f / g_denom[b * UP + u];
        float4 a = ((const float4*)(g_updA + ((size_t)b * UP + u) * DD))[t];
        float4 c = ((const float4*)(g_updB + ((size_t)b * UP + u) * DD))[t];
        r = make_float4((a.x + c.x) * inv, (a.y + c.y) * inv,
                        (a.z + c.z) * inv, (a.w + c.w) * inv);
    } else {
        r = ((const float4*)(g_vmean + (size_t)b * DD))[t];
    }
    ((float4*)(out + (size_t)b * PER_BATCH + (size_t)l * DD))[t] = r;
}

// ---------------- launch ----------------
extern "C" void kernel_launch(void* const* d_in, const int* in_sizes, int n_in,
                              void* d_out, int out_size)
{
    const float* in1 = (const float*)d_in[0];
    const float* in2 = (const float*)d_in[1];
    const float* Wq  = (const float*)d_in[2];
    const float* bq  = (const float*)d_in[3];
    const float* Wk  = (const float*)d_in[4];
    const float* bk  = (const float*)d_in[5];
    const float* Wv  = (const float*)d_in[6];
    const float* bv  = (const float*)d_in[7];
    const int*   idx = (const int*)d_in[8];
    float* out = (float*)d_out;

    cudaFuncSetAttribute(k_proj,   cudaFuncAttributeMaxDynamicSharedMemorySize, SM_TOTAL);
    cudaFuncSetAttribute(k_qks,    cudaFuncAttributeMaxDynamicSharedMemorySize, SM_TOTAL);
    cudaFuncSetAttribute(k_scores, cudaFuncAttributeMaxDynamicSharedMemorySize, SM_TOTAL);
    cudaFuncSetAttribute(k_upd,    cudaFuncAttributeMaxDynamicSharedMemorySize, SM_TOTAL);

    cudaStream_t s1 = g_str.s1;

    k_convW<<<3072, 256>>>(Wq, Wk, Wv);
    k_convX<<<dim3(LQ / 32, CC / 32, NB), dim3(32, 8)>>>(in1, in2);

    // merged projections: Q, K, V in one launch (3072 CTAs)
    k_proj<<<dim3(LQ / 256, DD / 128, NB * 3), 256, SM_TOTAL>>>(bq, bk, bv);

    // fork V branch onto s1: transV -> vmean (independent of qks/topk/scores)
    cudaEventRecord(g_str.eFork, 0);
    cudaStreamWaitEvent(s1, g_str.eFork, 0);
    k_transV<<<dim3(DD / 32, LQ / 32, NB), dim3(32, 8), 0, s1>>>();
    cudaEventRecord(g_str.eVT, s1);
    k_vmean1<<<dim3(16, NB), 512, 0, s1>>>();
    k_vmean2<<<NB, 512, 0, s1>>>();
    cudaEventRecord(g_str.eVM, s1);

    // main chain continues on default stream
    k_gather_ks<<<dim3(UP, NB), 128>>>(idx);
    k_qks<<<dim3(UP / 256, LQ / 128, NB), 256, SM_TOTAL>>>();
    k_topk<<<NB, 1024>>>();
    k_gather_qr<<<dim3(UP, NB), 128>>>();

    k_scores<<<dim3(LQ / 256, UP / 128, NB), 256, SM_TOTAL>>>();
    k_softmax<<<dim3(UP, NB), 256>>>();

    cudaStreamWaitEvent(0, g_str.eVT, 0);    // upd needs VT
    k_upd<<<dim3(DD / 256, UP / 128, NB * 2), 256, SM_TOTAL>>>();

    cudaStreamWaitEvent(0, g_str.eVM, 0);    // output needs vmean
    k_output<<<dim3(LQ, NB), 128>>>(out);
}

// round 14
// speedup vs baseline: 1.0080x; 1.0080x over previous
#include <cuda_runtime.h>
#include <cuda_bf16.h>
#include <math_constants.h>
#include <cstdint>
#include <mma.h>

using namespace nvcuda;

#define NB 16
#define LQ 4096          // L
#define DD 512           // D
#define CC 512           // 2*Cin
#define UU 450           // top-k count
#define UP 512           // padded U
#define PER_BATCH (LQ*DD)

typedef __nv_bfloat16 bf16;

// ---------------- device scratch ----------------
__device__ float g_v[(size_t)NB*PER_BATCH];     // proj-V flat [o][4096] == v[l][d]
__device__ float g_S[(size_t)NB*PER_BATCH];     // scores [u][4096] (fp32)
__device__ float g_updA[(size_t)NB*UP*DD];      // upd partial K half 0
__device__ float g_updB[(size_t)NB*UP*DD];      // upd partial K half 1
__device__ int   g_topk[NB*UP];
__device__ int   g_ulookup[NB*LQ];              // l -> u or -1
__device__ float2 g_Mpart[NB*LQ*2];             // qks fused max/sum partials (2 N-tiles)
__device__ float g_smaxp[NB*UP*16];             // scores fused row-max partials (16 N-tiles)
__device__ float g_vpart2[(size_t)NB*128*DD];   // transV-fused vmean partials [b][ltile][d]
__device__ float g_vmean[NB*DD];
__device__ float g_denom[NB*UP];

__device__ __align__(16) bf16 g_Whi[3*DD*CC],            g_Wlo[3*DD*CC];
__device__ __align__(16) bf16 g_XThi[(size_t)NB*LQ*CC],  g_XTlo[(size_t)NB*LQ*CC];  // [s][c]
__device__ __align__(16) bf16 g_Qhi[(size_t)NB*LQ*DD],   g_Qlo[(size_t)NB*LQ*DD];   // flat: [o][4096] == q[l][d]
__device__ __align__(16) bf16 g_Khi[(size_t)NB*LQ*DD],   g_Klo[(size_t)NB*LQ*DD];   // flat
__device__ __align__(16) bf16 g_KShi[(size_t)NB*UP*DD],  g_KSlo[(size_t)NB*UP*DD];  // [s][d]
__device__ __align__(16) bf16 g_QRhi[(size_t)NB*UP*DD],  g_QRlo[(size_t)NB*UP*DD];  // [u][d]
__device__ __align__(16) bf16 g_SEhi[(size_t)NB*UP*LQ],  g_SElo[(size_t)NB*UP*LQ];  // [u][l]
__device__ __align__(16) bf16 g_VThi[(size_t)NB*DD*LQ],  g_VTlo[(size_t)NB*DD*LQ];  // [d][l]

// ---------------- helpers ----------------
__device__ __forceinline__ uint32_t smem_u32(const void* p) {
    uint32_t a;
    asm("{ .reg .u64 t; cvta.to.shared.u64 t, %1; cvt.u32.u64 %0, t; }" : "=r"(a) : "l"(p));
    return a;
}
__device__ __forceinline__ void cpa16(uint32_t dst, const void* src) {
    asm volatile("cp.async.cg.shared.global [%0], [%1], 16;" :: "r"(dst), "l"(src));
}
__device__ __forceinline__ void cp_commit() { asm volatile("cp.async.commit_group;" ::: "memory"); }
template<int N> __device__ __forceinline__ void cp_wait() {
    asm volatile("cp.async.wait_group %0;" :: "n"(N) : "memory");
}
__device__ __forceinline__ bf16 hi_of(float x) { return __float2bfloat16(x); }
__device__ __forceinline__ bf16 lo_of(float x, bf16 h) { return __float2bfloat16(x - __bfloat162float(h)); }

// ============================================================================
// wmma GEMM: CTA tile 128(M) x 256(N), BK=32, 8 warps (2M x 4N), warp 64x64,
// double-buffered cp.async. A [Mtot][lda] K-major hi/lo, B [Ntot][lda] hi/lo.
// NPROD=3: Ah*Bh + Ah*Bl + Al*Bh.  NPROD=2: Ah*Bh + Al*Bh (Blo unloaded).
// EPI: 2 qks: NO C write; masked (col<UU) row max/sum partials -> part(float2)
//      3 scores: alpha fp32 + row-max partials -> part(float)
//      4 plain fp32 (upd partial)
//      5 proj: row-bias; Chi!=null -> bf16 split else fp32
// ============================================================================
#define SA 48                     // smem row stride in halfs (96B)
#define ARR_A (128*SA*2)          // 12288 B
#define ARR_B (256*SA*2)          // 24576 B
#define STAGE (2*ARR_A + 2*ARR_B) // 73728 B
#define SM_TOTAL (2*STAGE)        // 147456 B (C-stage 128*260*4=133120 reuses)

template<int EPI, int NPROD>
__device__ __forceinline__ void gemm_wmma(
    const bf16* __restrict__ Ahi, const bf16* __restrict__ Alo,
    const bf16* __restrict__ Bhi, const bf16* __restrict__ Blo,
    int KEXT, int lda,
    float* __restrict__ C, bf16* __restrict__ Chi, bf16* __restrict__ Clo, int ldc,
    const float* __restrict__ aux, float alpha, float* __restrict__ part)
{
    extern __shared__ char sm[];
    const uint32_t smb = smem_u32(sm);
    const int tid = threadIdx.x, w = tid >> 5;
    const int mw = w >> 2, nw = w & 3;           // 2M x 4N warp grid
    const int m0 = blockIdx.y * 128, n0 = blockIdx.x * 256;
    const int NS = KEXT >> 5;

    wmma::fragment<wmma::accumulator, 16, 16, 16, float> fc[4][4];
    #pragma unroll
    for (int i = 0; i < 4; i++)
        #pragma unroll
        for (int j = 0; j < 4; j++) wmma::fill_fragment(fc[i][j], 0.f);

    auto load_stage = [&](int s, int bufb) {
        const int k0 = s << 5;
        const uint32_t base = smb + bufb * STAGE;
        #pragma unroll
        for (int q = 0; q < 2; q++) {
            const bf16* src = q ? Alo : Ahi;
            const uint32_t dst = base + q * ARR_A;
            #pragma unroll
            for (int c0 = 0; c0 < 512; c0 += 256) {
                int c = c0 + tid;
                int row = c >> 2, col = c & 3;
                cpa16(dst + row * 96 + col * 16,
                      src + (size_t)(m0 + row) * lda + k0 + col * 8);
            }
        }
        #pragma unroll
        for (int q = 0; q < 2; q++) {
            if (NPROD == 2 && q == 1) break;     // skip Blo entirely
            const bf16* src = q ? Blo : Bhi;
            const uint32_t dst = base + 2 * ARR_A + q * ARR_B;
            #pragma unroll
            for (int c0 = 0; c0 < 1024; c0 += 256) {
                int c = c0 + tid;
                int row = c >> 2, col = c & 3;
                cpa16(dst + row * 96 + col * 16,
                      src + (size_t)(n0 + row) * lda + k0 + col * 8);
            }
        }
        cp_commit();
    };

    load_stage(0, 0);

    for (int s = 0; s < NS; s++) {
        const int b = s & 1;
        if (s + 1 < NS) { load_stage(s + 1, b ^ 1); cp_wait<1>(); }
        else            { cp_wait<0>(); }
        __syncthreads();

        const bf16* sAh = (const bf16*)(sm + b * STAGE);
        const bf16* sAl = (const bf16*)(sm + b * STAGE + ARR_A);
        const bf16* sBh = (const bf16*)(sm + b * STAGE + 2 * ARR_A);
        const bf16* sBl = (const bf16*)(sm + b * STAGE + 2 * ARR_A + ARR_B);

        #pragma unroll
        for (int ks = 0; ks < 2; ks++) {
            wmma::fragment<wmma::matrix_a, 16, 16, 16, bf16, wmma::row_major> fah[4], fal[4];
            #pragma unroll
            for (int i = 0; i < 4; i++) {
                const int r = mw * 64 + i * 16;
                wmma::load_matrix_sync(fah[i], sAh + r * SA + ks * 16, SA);
                wmma::load_matrix_sync(fal[i], sAl + r * SA + ks * 16, SA);
            }
            #pragma unroll
            for (int j = 0; j < 4; j++) {
                wmma::fragment<wmma::matrix_b, 16, 16, 16, bf16, wmma::col_major> fbh, fbl;
                const int n = nw * 64 + j * 16;
                wmma::load_matrix_sync(fbh, sBh + n * SA + ks * 16, SA);
                if (NPROD == 3)
                    wmma::load_matrix_sync(fbl, sBl + n * SA + ks * 16, SA);
                // products-outer: same per-accumulator order -> bit-identical,
                // dependent-HMMA distance = 4.
                #pragma unroll
                for (int i = 0; i < 4; i++)
                    wmma::mma_sync(fc[i][j], fah[i], fbh, fc[i][j]);
                if (NPROD == 3) {
                    #pragma unroll
                    for (int i = 0; i < 4; i++)
                        wmma::mma_sync(fc[i][j], fah[i], fbl, fc[i][j]);
                }
                #pragma unroll
                for (int i = 0; i < 4; i++)
                    wmma::mma_sync(fc[i][j], fal[i], fbh, fc[i][j]);
            }
        }
        __syncthreads();
    }

    // ---- epilogue via smem C-stage (known layout), 128 x 260 fp32 ----
    float* csm = (float*)sm;
    #pragma unroll
    for (int i = 0; i < 4; i++)
        #pragma unroll
        for (int j = 0; j < 4; j++)
            wmma::store_matrix_sync(csm + (mw*64 + i*16) * 260 + nw*64 + j*16,
                                    fc[i][j], 260, wmma::mem_row_major);
    __syncthreads();

    const int r = tid >> 1, gm = m0 + r;
    const int cb0 = (tid & 1) * 128;
    const float* src = csm + r * 260 + cb0;

    if (EPI == 5) {                       // proj: row bias; split or fp32
        const float add = aux[gm];
        if (Chi) {
            #pragma unroll
            for (int g = 0; g < 4; g++) {
                ushort hs[32], ls[32];
                #pragma unroll
                for (int c = 0; c < 32; c++) {
                    float v = src[g * 32 + c] + add;
                    bf16 h = hi_of(v);
                    hs[c] = __bfloat16_as_ushort(h);
                    ls[c] = __bfloat16_as_ushort(lo_of(v, h));
                }
                bf16* ph = Chi + (size_t)gm * ldc + n0 + cb0 + g * 32;
                bf16* pl = Clo + (size_t)gm * ldc + n0 + cb0 + g * 32;
                #pragma unroll
                for (int j = 0; j < 4; j++) {
                    *(uint4*)(ph + j * 8) = *(uint4*)&hs[j * 8];
                    *(uint4*)(pl + j * 8) = *(uint4*)&ls[j * 8];
                }
            }
        } else {
            float* pc = C + (size_t)gm * ldc + n0 + cb0;
            #pragma unroll
            for (int j = 0; j < 32; j++) {
                float4 v = *(const float4*)(src + j * 4);
                v.x += add; v.y += add; v.z += add; v.w += add;
                *(float4*)(pc + j * 4) = v;
            }
        }
    } else if (EPI == 2) {                // qks: masked row max/sum, no C write
        float mx = -CUDART_INF_F, smv = 0.f;
        #pragma unroll 8
        for (int c = 0; c < 128; c++) {
            int scol = n0 + cb0 + c;
            if (scol < UU) { float v = src[c]; mx = fmaxf(mx, v); smv += v; }
        }
        float mx2 = fmaxf(mx, __shfl_xor_sync(0xffffffffu, mx, 1));
        float sm2 = smv + __shfl_xor_sync(0xffffffffu, smv, 1);
        if ((tid & 1) == 0)
            ((float2*)part)[gm * 2 + blockIdx.x] = make_float2(mx2, sm2);
    } else {
        float mul = (EPI == 3) ? alpha : 1.f;
        float* pc = C + (size_t)gm * ldc + n0 + cb0;
        float mx = -CUDART_INF_F;
        #pragma unroll
        for (int j = 0; j < 32; j++) {
            float4 v = *(const float4*)(src + j * 4);
            v.x *= mul; v.y *= mul; v.z *= mul; v.w *= mul;
            if (EPI == 3) mx = fmaxf(mx, fmaxf(fmaxf(v.x, v.y), fmaxf(v.z, v.w)));
            *(float4*)(pc + j * 4) = v;
        }
        if (EPI == 3) {
            float mx2 = fmaxf(mx, __shfl_xor_sync(0xffffffffu, mx, 1));
            if ((tid & 1) == 0) part[gm * 16 + blockIdx.x] = mx2;
        }
    }
}

// ---------------- merged proj kernel (Q, K, V in one launch) ----------------
__global__ __launch_bounds__(256, 1) void k_proj(const float* __restrict__ bq,
                                                 const float* __restrict__ bk,
                                                 const float* __restrict__ bv)
{
    int z = blockIdx.z, mi = z >> 4, b = z & 15;
    const float* bias = (mi == 0) ? bq : (mi == 1) ? bk : bv;
    bf16 *Ch = nullptr, *Cl = nullptr;
    float* C = nullptr;
    if (mi == 0)      { Ch = g_Qhi + (size_t)b*PER_BATCH; Cl = g_Qlo + (size_t)b*PER_BATCH; }
    else if (mi == 1) { Ch = g_Khi + (size_t)b*PER_BATCH; Cl = g_Klo + (size_t)b*PER_BATCH; }
    else              { C  = g_v   + (size_t)b*PER_BATCH; }
    gemm_wmma<5, 3>(g_Whi + (size_t)mi*DD*CC, g_Wlo + (size_t)mi*DD*CC,
                    g_XThi + (size_t)b*LQ*CC, g_XTlo + (size_t)b*LQ*CC, CC, CC,
                    C, Ch, Cl, LQ, bias, 1.f, nullptr);
}
// QKs fused: only max/sum partials, no matrix output (3-product: feeds top-k)
__global__ __launch_bounds__(256, 1) void k_qks()
{
    int b = blockIdx.z;
    gemm_wmma<2, 3>(g_Qhi + (size_t)b*PER_BATCH, g_Qlo + (size_t)b*PER_BATCH,
                    g_KShi + (size_t)b*UP*DD, g_KSlo + (size_t)b*UP*DD, DD, DD,
                    nullptr, nullptr, nullptr, UP, nullptr, 1.f,
                    (float*)(g_Mpart + (size_t)b*LQ*2));
}
// scores: 2-product (QR split x K_hi)
__global__ __launch_bounds__(256, 1) void k_scores()
{
    int b = blockIdx.z;
    gemm_wmma<3, 2>(g_QRhi + (size_t)b*UP*DD, g_QRlo + (size_t)b*UP*DD,
                    g_Khi + (size_t)b*PER_BATCH, nullptr, DD, DD,
                    g_S + (size_t)b*PER_BATCH, nullptr, nullptr, LQ, nullptr,
                    0.044194173824159216f, g_smaxp + (size_t)b*UP*16);
}
// upd partial: K split in halves; z = half*16 + b
__global__ __launch_bounds__(256, 1) void k_upd()
{
    int z = blockIdx.z, h = z >> 4, b = z & 15;
    const size_t koff = (size_t)h * 2048;
    float* dst = (h ? g_updB : g_updA) + (size_t)b*UP*DD;
    gemm_wmma<4, 3>(g_SEhi + (size_t)b*UP*LQ + koff, g_SElo + (size_t)b*UP*LQ + koff,
                    g_VThi + (size_t)b*DD*LQ + koff, g_VTlo + (size_t)b*DD*LQ + koff,
                    2048, LQ,
                    dst, nullptr, nullptr, DD, nullptr, 1.f, nullptr);
}

// ---------------- conversions ----------------
__global__ void k_convW(const float* __restrict__ Wq, const float* __restrict__ Wk,
                        const float* __restrict__ Wv)
{
    int i = blockIdx.x * 256 + threadIdx.x;
    int mi = i >> 18, r = i & 262143;
    const float* W = (mi == 0) ? Wq : (mi == 1) ? Wk : Wv;
    float x = W[r];
    bf16 h = hi_of(x);
    g_Whi[i] = h; g_Wlo[i] = lo_of(x, h);
}

__global__ void k_convX(const float* __restrict__ in1, const float* __restrict__ in2)
{
    __shared__ float t[32][33];
    int b = blockIdx.z, s0 = blockIdx.x * 32, c0 = blockIdx.y * 32;
    const float* src = (c0 < 256) ? (in1 + ((size_t)b * 256 + c0) * LQ)
                                  : (in2 + ((size_t)b * 256 + (c0 - 256)) * LQ);
    for (int i = threadIdx.y; i < 32; i += 8)
        t[i][threadIdx.x] = src[(size_t)i * LQ + s0 + threadIdx.x];
    __syncthreads();
    for (int i = threadIdx.y; i < 32; i += 8) {
        float x = t[threadIdx.x][i];
        bf16 h = hi_of(x);
        size_t off = ((size_t)b * LQ + s0 + i) * CC + c0 + threadIdx.x;
        g_XThi[off] = h; g_XTlo[off] = lo_of(x, h);
    }
}

// transV + fused vmean partials: g_v viewed v[l][d] -> VT[d][l] bf16 hi/lo,
// plus per-(b, l-tile, d) column-sum partials (deterministic order).
__global__ void k_transV()
{
    __shared__ float t[32][33];
    int b = blockIdx.z, d0 = blockIdx.x * 32, l0 = blockIdx.y * 32;
    const float* src = g_v + (size_t)b * PER_BATCH;
    for (int i = threadIdx.y; i < 32; i += 8)
        t[i][threadIdx.x] = src[(size_t)(l0 + i) * DD + d0 + threadIdx.x];
    __syncthreads();
    for (int i = threadIdx.y; i < 32; i += 8) {
        float x = t[threadIdx.x][i];      // t[li][di] read as [di=tx? no: t[l][d]] -> x = v[l0+tx? ...]
        bf16 h = hi_of(x);
        size_t off = ((size_t)b * DD + d0 + i) * LQ + l0 + threadIdx.x;
        g_VThi[off] = h; g_VTlo[off] = lo_of(x, h);
    }
    // wait: above writes VT[d0+i][l0+tx] = t[tx][i] = v[l0+tx][d0+i]  (correct, as before)
    __syncthreads();
    if (threadIdx.y == 0) {
        int di = threadIdx.x;
        float s = 0.f;
        #pragma unroll 8
        for (int li = 0; li < 32; li++) s += t[li][di];
        g_vpart2[((size_t)b * 128 + blockIdx.y) * DD + d0 + di] = s;
    }
}

// ---------------- gathers ----------------
__global__ void k_gather_ks(const int* __restrict__ idx)
{
    int b = blockIdx.y, s = blockIdx.x, t = threadIdx.x;
    size_t drow = ((size_t)b * UP + s) * DD;
    uint2* dh = (uint2*)(g_KShi + drow);
    uint2* dl = (uint2*)(g_KSlo + drow);
    if (s < UU) {
        size_t srow = ((size_t)b * LQ + idx[s]) * DD;
        dh[t] = ((const uint2*)(g_Khi + srow))[t];
        dl[t] = ((const uint2*)(g_Klo + srow))[t];
    } else {
        dh[t] = make_uint2(0, 0); dl[t] = make_uint2(0, 0);
    }
}
__global__ void k_gather_qr()
{
    int b = blockIdx.y, u = blockIdx.x, t = threadIdx.x;
    size_t drow = ((size_t)b * UP + u) * DD;
    uint2* dh = (uint2*)(g_QRhi + drow);
    uint2* dl = (uint2*)(g_QRlo + drow);
    if (u < UU) {
        size_t srow = ((size_t)b * LQ + g_topk[b * UP + u]) * DD;
        dh[t] = ((const uint2*)(g_Qhi + srow))[t];
        dl[t] = ((const uint2*)(g_Qlo + srow))[t];
    } else {
        dh[t] = make_uint2(0, 0); dl[t] = make_uint2(0, 0);
    }
}

// ---------------- top-k (M from qks partials) + inverse lookup ----------------
__global__ __launch_bounds__(1024) void k_topk()
{
    __shared__ float sv[LQ];
    __shared__ int   si[LQ];
    int b = blockIdx.x;
    for (int i = threadIdx.x; i < LQ; i += 1024) {
        float2 p0 = g_Mpart[(size_t)(b * LQ + i) * 2 + 0];
        float2 p1 = g_Mpart[(size_t)(b * LQ + i) * 2 + 1];
        sv[i] = fmaxf(p0.x, p1.x) - (p0.y + p1.y) * (1.0f / LQ);
        si[i] = i;
        g_ulookup[b * LQ + i] = -1;
    }
    __syncthreads();
    for (int k = 2; k <= LQ; k <<= 1) {
        for (int j = k >> 1; j > 0; j >>= 1) {
            for (int t = threadIdx.x; t < LQ / 2; t += 1024) {
                int i = ((t & ~(j - 1)) << 1) | (t & (j - 1));
                int ixj = i | j;
                bool desc = ((i & k) == 0);
                float a = sv[i], c = sv[ixj];
                bool sw = desc ? (a < c) : (a > c);
                if (sw) { sv[i] = c; sv[ixj] = a; int ti = si[i]; si[i] = si[ixj]; si[ixj] = ti; }
            }
            __syncthreads();
        }
    }
    for (int u = threadIdx.x; u < UU; u += 1024) {
        g_topk[b * UP + u] = si[u];
        g_ulookup[b * LQ + si[u]] = u;
    }
}

// ---------------- softmax (single pass; max from scores partials) ----------------
__global__ __launch_bounds__(256) void k_softmax()
{
    int b = blockIdx.y, u = blockIdx.x, t = threadIdx.x;
    size_t off = (size_t)b * PER_BATCH + (size_t)u * LQ;
    bf16* eh = g_SEhi + off;
    bf16* el = g_SElo + off;
    if (u >= UU) {
        for (int l = t; l < LQ; l += 256) { eh[l] = __ushort_as_bfloat16(0); el[l] = __ushort_as_bfloat16(0); }
        if (t == 0) g_denom[b * UP + u] = 1.f;
        return;
    }
    const float* mp = g_smaxp + ((size_t)b * UP + u) * 16;
    float mx = -CUDART_INF_F;
    #pragma unroll
    for (int i = 0; i < 16; i++) mx = fmaxf(mx, mp[i]);

    const float* row = g_S + off;
    __shared__ float red[256];
    float sm = 0.f;
    for (int l = t; l < LQ; l += 256) {
        float e = expf(row[l] - mx);
        bf16 h = hi_of(e);
        eh[l] = h; el[l] = lo_of(e, h);
        sm += e;
    }
    red[t] = sm; __syncthreads();
    for (int o = 128; o; o >>= 1) { if (t < o) red[t] += red[t + o]; __syncthreads(); }
    if (t == 0) g_denom[b * UP + u] = red[0];
}

// ---------------- vmean: sum 128 l-tile partials per (b,d) ----------------
__global__ void k_vmean2()
{
    int b = blockIdx.x, d = threadIdx.x;
    float acc = 0.f;
    #pragma unroll 8
    for (int t = 0; t < 128; t++)
        acc += g_vpart2[((size_t)b * 128 + t) * DD + d];
    g_vmean[b * DD + d] = acc * (1.0f / LQ);
}

// ---------------- fused output: vmean broadcast or (updA+updB)/denom ----------------
__global__ void k_output(float* __restrict__ out)
{
    int b = blockIdx.y, l = blockIdx.x, t = threadIdx.x;
    int u = g_ulookup[b * LQ + l];
    float4 r;
    if (u >= 0) {
        float inv = 1.f / g_denom[b * UP + u];
        float4 a = ((const float4*)(g_updA + ((size_t)b * UP + u) * DD))[t];
        float4 c = ((const float4*)(g_updB + ((size_t)b * UP + u) * DD))[t];
        r = make_float4((a.x + c.x) * inv, (a.y + c.y) * inv,
                        (a.z + c.z) * inv, (a.w + c.w) * inv);
    } else {
        r = ((const float4*)(g_vmean + (size_t)b * DD))[t];
    }
    ((float4*)(out + (size_t)b * PER_BATCH + (size_t)l * DD))[t] = r;
}

// ---------------- launch (single stream; graph-linear) ----------------
extern "C" void kernel_launch(void* const* d_in, const int* in_sizes, int n_in,
                              void* d_out, int out_size)
{
    const float* in1 = (const float*)d_in[0];
    const float* in2 = (const float*)d_in[1];
    const float* Wq  = (const float*)d_in[2];
    const float* bq  = (const float*)d_in[3];
    const float* Wk  = (const float*)d_in[4];
    const float* bk  = (const float*)d_in[5];
    const float* Wv  = (const float*)d_in[6];
    const float* bv  = (const float*)d_in[7];
    const int*   idx = (const int*)d_in[8];
    float* out = (float*)d_out;

    cudaFuncSetAttribute(k_proj,   cudaFuncAttributeMaxDynamicSharedMemorySize, SM_TOTAL);
    cudaFuncSetAttribute(k_qks,    cudaFuncAttributeMaxDynamicSharedMemorySize, SM_TOTAL);
    cudaFuncSetAttribute(k_scores, cudaFuncAttributeMaxDynamicSharedMemorySize, SM_TOTAL);
    cudaFuncSetAttribute(k_upd,    cudaFuncAttributeMaxDynamicSharedMemorySize, SM_TOTAL);

    k_convW<<<3072, 256>>>(Wq, Wk, Wv);
    k_convX<<<dim3(LQ / 32, CC / 32, NB), dim3(32, 8)>>>(in1, in2);

    // merged projections: Q, K, V in one launch (3072 CTAs)
    k_proj<<<dim3(LQ / 256, DD / 128, NB * 3), 256, SM_TOTAL>>>(bq, bk, bv);

    k_transV<<<dim3(DD / 32, LQ / 32, NB), dim3(32, 8)>>>();
    k_vmean2<<<NB, 512>>>();

    k_gather_ks<<<dim3(UP, NB), 128>>>(idx);
    k_qks<<<dim3(UP / 256, LQ / 128, NB), 256, SM_TOTAL>>>();
    k_topk<<<NB, 1024>>>();
    k_gather_qr<<<dim3(UP, NB), 128>>>();

    k_scores<<<dim3(LQ / 256, UP / 128, NB), 256, SM_TOTAL>>>();
    k_softmax<<<dim3(UP, NB), 256>>>();
    k_upd<<<dim3(DD / 256, UP / 128, NB * 2), 256, SM_TOTAL>>>();

    k_output<<<dim3(LQ, NB), 128>>>(out);
}

// round 15
// speedup vs baseline: 1.0317x; 1.0235x over previous
#include <cuda_runtime.h>
#include <cuda_bf16.h>
#include <math_constants.h>
#include <cstdint>
#include <mma.h>

using namespace nvcuda;

#define NB 16
#define LQ 4096          // L
#define DD 512           // D
#define CC 512           // 2*Cin
#define UU 450           // top-k count
#define UP 512           // padded U
#define PER_BATCH (LQ*DD)

typedef __nv_bfloat16 bf16;

// ---------------- device scratch ----------------
__device__ float g_v[(size_t)NB*PER_BATCH];     // proj-V flat [o][4096] == v[l][d]
__device__ float g_updA[(size_t)NB*UP*DD];      // upd partial K half 0
__device__ float g_updB[(size_t)NB*UP*DD];      // upd partial K half 1
__device__ int   g_topk[NB*UP];
__device__ int   g_ulookup[NB*LQ];              // l -> u or -1
__device__ float2 g_Mpart[NB*LQ*2];             // qks fused max/sum partials (2 N-tiles)
__device__ float g_spart[NB*UP*16];             // scores fused row exp-sum partials (16 N-tiles)
__device__ float g_vpart2[(size_t)NB*64*DD];    // transV-fused vmean partials [b][ltile64][d]
__device__ float g_vmean[NB*DD];
__device__ float g_denom[NB*UP];

__device__ __align__(16) bf16 g_Whi[3*DD*CC],            g_Wlo[3*DD*CC];
__device__ __align__(16) bf16 g_XThi[(size_t)NB*LQ*CC],  g_XTlo[(size_t)NB*LQ*CC];  // [s][c]
__device__ __align__(16) bf16 g_Qhi[(size_t)NB*LQ*DD],   g_Qlo[(size_t)NB*LQ*DD];   // flat: [o][4096] == q[l][d]
__device__ __align__(16) bf16 g_Khi[(size_t)NB*LQ*DD],   g_Klo[(size_t)NB*LQ*DD];   // flat
__device__ __align__(16) bf16 g_KShi[(size_t)NB*UP*DD],  g_KSlo[(size_t)NB*UP*DD];  // [s][d]
__device__ __align__(16) bf16 g_QRhi[(size_t)NB*UP*DD],  g_QRlo[(size_t)NB*UP*DD];  // [u][d]
__device__ __align__(16) bf16 g_SEhi[(size_t)NB*UP*LQ],  g_SElo[(size_t)NB*UP*LQ];  // [u][l] unnormalized exp
__device__ __align__(16) bf16 g_VThi[(size_t)NB*DD*LQ],  g_VTlo[(size_t)NB*DD*LQ];  // [d][l]

// ---------------- helpers ----------------
__device__ __forceinline__ uint32_t smem_u32(const void* p) {
    uint32_t a;
    asm("{ .reg .u64 t; cvta.to.shared.u64 t, %1; cvt.u32.u64 %0, t; }" : "=r"(a) : "l"(p));
    return a;
}
__device__ __forceinline__ void cpa16(uint32_t dst, const void* src) {
    asm volatile("cp.async.cg.shared.global [%0], [%1], 16;" :: "r"(dst), "l"(src));
}
__device__ __forceinline__ void cp_commit() { asm volatile("cp.async.commit_group;" ::: "memory"); }
template<int N> __device__ __forceinline__ void cp_wait() {
    asm volatile("cp.async.wait_group %0;" :: "n"(N) : "memory");
}
__device__ __forceinline__ bf16 hi_of(float x) { return __float2bfloat16(x); }
__device__ __forceinline__ bf16 lo_of(float x, bf16 h) { return __float2bfloat16(x - __bfloat162float(h)); }

// ============================================================================
// wmma GEMM: CTA tile 128(M) x 256(N), BK=32, 8 warps (2M x 4N), warp 64x64,
// double-buffered cp.async. A [Mtot][lda] K-major hi/lo, B [Ntot][lda] hi/lo.
// NPROD=3: Ah*Bh + Ah*Bl + Al*Bh.  NPROD=2: Ah*Bh + Al*Bh (Blo unloaded).
// EPI: 2 qks: NO C write; masked (col<UU) row max/sum partials -> part(float2)
//      3 scores: e=__expf(v*alpha) -> bf16 split Chi/Clo + row-sum partials
//      4 plain fp32 (upd partial)
//      5 proj: row-bias; Chi!=null -> bf16 split else fp32
// ============================================================================
#define SA 48                     // smem row stride in halfs (96B)
#define ARR_A (128*SA*2)          // 12288 B
#define ARR_B (256*SA*2)          // 24576 B
#define STAGE (2*ARR_A + 2*ARR_B) // 73728 B
#define SM_TOTAL (2*STAGE)        // 147456 B (C-stage 128*260*4=133120 reuses)

template<int EPI, int NPROD>
__device__ __forceinline__ void gemm_wmma(
    const bf16* __restrict__ Ahi, const bf16* __restrict__ Alo,
    const bf16* __restrict__ Bhi, const bf16* __restrict__ Blo,
    int KEXT, int lda,
    float* __restrict__ C, bf16* __restrict__ Chi, bf16* __restrict__ Clo, int ldc,
    const float* __restrict__ aux, float alpha, float* __restrict__ part)
{
    extern __shared__ char sm[];
    const uint32_t smb = smem_u32(sm);
    const int tid = threadIdx.x, w = tid >> 5;
    const int mw = w >> 2, nw = w & 3;           // 2M x 4N warp grid
    const int m0 = blockIdx.y * 128, n0 = blockIdx.x * 256;
    const int NS = KEXT >> 5;

    wmma::fragment<wmma::accumulator, 16, 16, 16, float> fc[4][4];
    #pragma unroll
    for (int i = 0; i < 4; i++)
        #pragma unroll
        for (int j = 0; j < 4; j++) wmma::fill_fragment(fc[i][j], 0.f);

    auto load_stage = [&](int s, int bufb) {
        const int k0 = s << 5;
        const uint32_t base = smb + bufb * STAGE;
        #pragma unroll
        for (int q = 0; q < 2; q++) {
            const bf16* src = q ? Alo : Ahi;
            const uint32_t dst = base + q * ARR_A;
            #pragma unroll
            for (int c0 = 0; c0 < 512; c0 += 256) {
                int c = c0 + tid;
                int row = c >> 2, col = c & 3;
                cpa16(dst + row * 96 + col * 16,
                      src + (size_t)(m0 + row) * lda + k0 + col * 8);
            }
        }
        #pragma unroll
        for (int q = 0; q < 2; q++) {
            if (NPROD == 2 && q == 1) break;     // skip Blo entirely
            const bf16* src = q ? Blo : Bhi;
            const uint32_t dst = base + 2 * ARR_A + q * ARR_B;
            #pragma unroll
            for (int c0 = 0; c0 < 1024; c0 += 256) {
                int c = c0 + tid;
                int row = c >> 2, col = c & 3;
                cpa16(dst + row * 96 + col * 16,
                      src + (size_t)(n0 + row) * lda + k0 + col * 8);
            }
        }
        cp_commit();
    };

    load_stage(0, 0);

    for (int s = 0; s < NS; s++) {
        const int b = s & 1;
        if (s + 1 < NS) { load_stage(s + 1, b ^ 1); cp_wait<1>(); }
        else            { cp_wait<0>(); }
        __syncthreads();

        const bf16* sAh = (const bf16*)(sm + b * STAGE);
        const bf16* sAl = (const bf16*)(sm + b * STAGE + ARR_A);
        const bf16* sBh = (const bf16*)(sm + b * STAGE + 2 * ARR_A);
        const bf16* sBl = (const bf16*)(sm + b * STAGE + 2 * ARR_A + ARR_B);

        #pragma unroll
        for (int ks = 0; ks < 2; ks++) {
            wmma::fragment<wmma::matrix_a, 16, 16, 16, bf16, wmma::row_major> fah[4], fal[4];
            #pragma unroll
            for (int i = 0; i < 4; i++) {
                const int r = mw * 64 + i * 16;
                wmma::load_matrix_sync(fah[i], sAh + r * SA + ks * 16, SA);
                wmma::load_matrix_sync(fal[i], sAl + r * SA + ks * 16, SA);
            }
            #pragma unroll
            for (int j = 0; j < 4; j++) {
                wmma::fragment<wmma::matrix_b, 16, 16, 16, bf16, wmma::col_major> fbh, fbl;
                const int n = nw * 64 + j * 16;
                wmma::load_matrix_sync(fbh, sBh + n * SA + ks * 16, SA);
                if (NPROD == 3)
                    wmma::load_matrix_sync(fbl, sBl + n * SA + ks * 16, SA);
                #pragma unroll
                for (int i = 0; i < 4; i++)
                    wmma::mma_sync(fc[i][j], fah[i], fbh, fc[i][j]);
                if (NPROD == 3) {
                    #pragma unroll
                    for (int i = 0; i < 4; i++)
                        wmma::mma_sync(fc[i][j], fah[i], fbl, fc[i][j]);
                }
                #pragma unroll
                for (int i = 0; i < 4; i++)
                    wmma::mma_sync(fc[i][j], fal[i], fbh, fc[i][j]);
            }
        }
        __syncthreads();
    }

    // ---- epilogue via smem C-stage (known layout), 128 x 260 fp32 ----
    float* csm = (float*)sm;
    #pragma unroll
    for (int i = 0; i < 4; i++)
        #pragma unroll
        for (int j = 0; j < 4; j++)
            wmma::store_matrix_sync(csm + (mw*64 + i*16) * 260 + nw*64 + j*16,
                                    fc[i][j], 260, wmma::mem_row_major);
    __syncthreads();

    const int r = tid >> 1, gm = m0 + r;
    const int cb0 = (tid & 1) * 128;
    const float* src = csm + r * 260 + cb0;

    if (EPI == 5) {                       // proj: row bias; split or fp32
        const float add = aux[gm];
        if (Chi) {
            #pragma unroll
            for (int g = 0; g < 4; g++) {
                ushort hs[32], ls[32];
                #pragma unroll
                for (int c = 0; c < 32; c++) {
                    float v = src[g * 32 + c] + add;
                    bf16 h = hi_of(v);
                    hs[c] = __bfloat16_as_ushort(h);
                    ls[c] = __bfloat16_as_ushort(lo_of(v, h));
                }
                bf16* ph = Chi + (size_t)gm * ldc + n0 + cb0 + g * 32;
                bf16* pl = Clo + (size_t)gm * ldc + n0 + cb0 + g * 32;
                #pragma unroll
                for (int j = 0; j < 4; j++) {
                    *(uint4*)(ph + j * 8) = *(uint4*)&hs[j * 8];
                    *(uint4*)(pl + j * 8) = *(uint4*)&ls[j * 8];
                }
            }
        } else {
            float* pc = C + (size_t)gm * ldc + n0 + cb0;
            #pragma unroll
            for (int j = 0; j < 32; j++) {
                float4 v = *(const float4*)(src + j * 4);
                v.x += add; v.y += add; v.z += add; v.w += add;
                *(float4*)(pc + j * 4) = v;
            }
        }
    } else if (EPI == 2) {                // qks: masked row max/sum, no C write
        float mx = -CUDART_INF_F, smv = 0.f;
        #pragma unroll 8
        for (int c = 0; c < 128; c++) {
            int scol = n0 + cb0 + c;
            if (scol < UU) { float v = src[c]; mx = fmaxf(mx, v); smv += v; }
        }
        float mx2 = fmaxf(mx, __shfl_xor_sync(0xffffffffu, mx, 1));
        float sm2 = smv + __shfl_xor_sync(0xffffffffu, smv, 1);
        if ((tid & 1) == 0)
            ((float2*)part)[gm * 2 + blockIdx.x] = make_float2(mx2, sm2);
    } else if (EPI == 3) {                // scores: fused exp -> bf16 split + sum
        float sum = 0.f;
        #pragma unroll
        for (int g = 0; g < 4; g++) {
            ushort hs[32], ls[32];
            #pragma unroll
            for (int c = 0; c < 32; c++) {
                float e = __expf(src[g * 32 + c] * alpha);
                bf16 h = hi_of(e);
                hs[c] = __bfloat16_as_ushort(h);
                ls[c] = __bfloat16_as_ushort(lo_of(e, h));
                sum += e;
            }
            bf16* ph = Chi + (size_t)gm * ldc + n0 + cb0 + g * 32;
            bf16* pl = Clo + (size_t)gm * ldc + n0 + cb0 + g * 32;
            #pragma unroll
            for (int j = 0; j < 4; j++) {
                *(uint4*)(ph + j * 8) = *(uint4*)&hs[j * 8];
                *(uint4*)(pl + j * 8) = *(uint4*)&ls[j * 8];
            }
        }
        float s2 = sum + __shfl_xor_sync(0xffffffffu, sum, 1);
        if ((tid & 1) == 0) part[gm * 16 + blockIdx.x] = s2;
    } else {                              // EPI 4: plain fp32
        float* pc = C + (size_t)gm * ldc + n0 + cb0;
        #pragma unroll
        for (int j = 0; j < 32; j++)
            *(float4*)(pc + j * 4) = *(const float4*)(src + j * 4);
    }
}

// ---------------- merged proj kernel (Q, K, V in one launch) ----------------
__global__ __launch_bounds__(256, 1) void k_proj(const float* __restrict__ bq,
                                                 const float* __restrict__ bk,
                                                 const float* __restrict__ bv)
{
    int z = blockIdx.z, mi = z >> 4, b = z & 15;
    const float* bias = (mi == 0) ? bq : (mi == 1) ? bk : bv;
    bf16 *Ch = nullptr, *Cl = nullptr;
    float* C = nullptr;
    if (mi == 0)      { Ch = g_Qhi + (size_t)b*PER_BATCH; Cl = g_Qlo + (size_t)b*PER_BATCH; }
    else if (mi == 1) { Ch = g_Khi + (size_t)b*PER_BATCH; Cl = g_Klo + (size_t)b*PER_BATCH; }
    else              { C  = g_v   + (size_t)b*PER_BATCH; }
    gemm_wmma<5, 3>(g_Whi + (size_t)mi*DD*CC, g_Wlo + (size_t)mi*DD*CC,
                    g_XThi + (size_t)b*LQ*CC, g_XTlo + (size_t)b*LQ*CC, CC, CC,
                    C, Ch, Cl, LQ, bias, 1.f, nullptr);
}
// QKs fused: only max/sum partials, no matrix output
__global__ __launch_bounds__(256, 1) void k_qks()
{
    int b = blockIdx.z;
    gemm_wmma<2, 3>(g_Qhi + (size_t)b*PER_BATCH, g_Qlo + (size_t)b*PER_BATCH,
                    g_KShi + (size_t)b*UP*DD, g_KSlo + (size_t)b*UP*DD, DD, DD,
                    nullptr, nullptr, nullptr, UP, nullptr, 1.f,
                    (float*)(g_Mpart + (size_t)b*LQ*2));
}
// scores: 2-product + fused exp -> SE bf16 split + denom partials
__global__ __launch_bounds__(256, 1) void k_scores()
{
    int b = blockIdx.z;
    gemm_wmma<3, 2>(g_QRhi + (size_t)b*UP*DD, g_QRlo + (size_t)b*UP*DD,
                    g_Khi + (size_t)b*PER_BATCH, nullptr, DD, DD,
                    nullptr, g_SEhi + (size_t)b*UP*LQ, g_SElo + (size_t)b*UP*LQ, LQ,
                    nullptr, 0.044194173824159216f, g_spart + (size_t)b*UP*16);
}
// upd partial: K split in halves; z = half*16 + b
__global__ __launch_bounds__(256, 1) void k_upd()
{
    int z = blockIdx.z, h = z >> 4, b = z & 15;
    const size_t koff = (size_t)h * 2048;
    float* dst = (h ? g_updB : g_updA) + (size_t)b*UP*DD;
    gemm_wmma<4, 3>(g_SEhi + (size_t)b*UP*LQ + koff, g_SElo + (size_t)b*UP*LQ + koff,
                    g_VThi + (size_t)b*DD*LQ + koff, g_VTlo + (size_t)b*DD*LQ + koff,
                    2048, LQ,
                    dst, nullptr, nullptr, DD, nullptr, 1.f, nullptr);
}

// ---------------- conversions ----------------
__global__ void k_convW(const float* __restrict__ Wq, const float* __restrict__ Wk,
                        const float* __restrict__ Wv)
{
    int i = blockIdx.x * 256 + threadIdx.x;
    int mi = i >> 18, r = i & 262143;
    const float* W = (mi == 0) ? Wq : (mi == 1) ? Wk : Wv;
    float x = W[r];
    bf16 h = hi_of(x);
    g_Whi[i] = h; g_Wlo[i] = lo_of(x, h);
}

__global__ void k_convX(const float* __restrict__ in1, const float* __restrict__ in2)
{
    __shared__ float t[32][33];
    int b = blockIdx.z, s0 = blockIdx.x * 32, c0 = blockIdx.y * 32;
    const float* src = (c0 < 256) ? (in1 + ((size_t)b * 256 + c0) * LQ)
                                  : (in2 + ((size_t)b * 256 + (c0 - 256)) * LQ);
    for (int i = threadIdx.y; i < 32; i += 8)
        t[i][threadIdx.x] = src[(size_t)i * LQ + s0 + threadIdx.x];
    __syncthreads();
    for (int i = threadIdx.y; i < 32; i += 8) {
        float x = t[threadIdx.x][i];
        bf16 h = hi_of(x);
        size_t off = ((size_t)b * LQ + s0 + i) * CC + c0 + threadIdx.x;
        g_XThi[off] = h; g_XTlo[off] = lo_of(x, h);
    }
}

// transV: 64(l) x 32(d) tiles, vectorized uint4 stores along l, fused vmean partials
__global__ void k_transV()
{
    __shared__ float t[64][33];
    int b = blockIdx.z, d0 = blockIdx.x * 32, l0 = blockIdx.y * 64;
    const float* src = g_v + (size_t)b * PER_BATCH;
    for (int i = threadIdx.y; i < 64; i += 8)
        t[i][threadIdx.x] = src[(size_t)(l0 + i) * DD + d0 + threadIdx.x];
    __syncthreads();
    {
        int tid = threadIdx.y * 32 + threadIdx.x;
        int di = tid >> 3, lg = tid & 7;         // di 0..31, lg 0..7 (8 l per group)
        ushort hs[8], ls[8];
        #pragma unroll
        for (int k = 0; k < 8; k++) {
            float x = t[lg * 8 + k][di];
            bf16 h = hi_of(x);
            hs[k] = __bfloat16_as_ushort(h);
            ls[k] = __bfloat16_as_ushort(lo_of(x, h));
        }
        size_t off = ((size_t)b * DD + d0 + di) * LQ + l0 + lg * 8;
        *(uint4*)(g_VThi + off) = *(uint4*)hs;
        *(uint4*)(g_VTlo + off) = *(uint4*)ls;
        if (lg == 0) {                            // vmean partial for this d
            float s = 0.f;
            #pragma unroll 8
            for (int li = 0; li < 64; li++) s += t[li][di];
            g_vpart2[((size_t)b * 64 + blockIdx.y) * DD + d0 + di] = s;
        }
    }
}

// ---------------- gathers ----------------
__global__ void k_gather_ks(const int* __restrict__ idx)
{
    int b = blockIdx.y, s = blockIdx.x, t = threadIdx.x;
    size_t drow = ((size_t)b * UP + s) * DD;
    uint2* dh = (uint2*)(g_KShi + drow);
    uint2* dl = (uint2*)(g_KSlo + drow);
    if (s < UU) {
        size_t srow = ((size_t)b * LQ + idx[s]) * DD;
        dh[t] = ((const uint2*)(g_Khi + srow))[t];
        dl[t] = ((const uint2*)(g_Klo + srow))[t];
    } else {
        dh[t] = make_uint2(0, 0); dl[t] = make_uint2(0, 0);
    }
}
__global__ void k_gather_qr()
{
    int b = blockIdx.y, u = blockIdx.x, t = threadIdx.x;
    size_t drow = ((size_t)b * UP + u) * DD;
    uint2* dh = (uint2*)(g_QRhi + drow);
    uint2* dl = (uint2*)(g_QRlo + drow);
    if (u < UU) {
        size_t srow = ((size_t)b * LQ + g_topk[b * UP + u]) * DD;
        dh[t] = ((const uint2*)(g_Qhi + srow))[t];
        dl[t] = ((const uint2*)(g_Qlo + srow))[t];
    } else {
        dh[t] = make_uint2(0, 0); dl[t] = make_uint2(0, 0);
    }
}

// ---------------- top-k (M from qks partials) + inverse lookup ----------------
__global__ __launch_bounds__(1024) void k_topk()
{
    __shared__ float sv[LQ];
    __shared__ int   si[LQ];
    int b = blockIdx.x;
    for (int i = threadIdx.x; i < LQ; i += 1024) {
        float2 p0 = g_Mpart[(size_t)(b * LQ + i) * 2 + 0];
        float2 p1 = g_Mpart[(size_t)(b * LQ + i) * 2 + 1];
        sv[i] = fmaxf(p0.x, p1.x) - (p0.y + p1.y) * (1.0f / LQ);
        si[i] = i;
        g_ulookup[b * LQ + i] = -1;
    }
    __syncthreads();
    for (int k = 2; k <= LQ; k <<= 1) {
        for (int j = k >> 1; j > 0; j >>= 1) {
            for (int t = threadIdx.x; t < LQ / 2; t += 1024) {
                int i = ((t & ~(j - 1)) << 1) | (t & (j - 1));
                int ixj = i | j;
                bool desc = ((i & k) == 0);
                float a = sv[i], c = sv[ixj];
                bool sw = desc ? (a < c) : (a > c);
                if (sw) { sv[i] = c; sv[ixj] = a; int ti = si[i]; si[i] = si[ixj]; si[ixj] = ti; }
            }
            __syncthreads();
        }
    }
    for (int u = threadIdx.x; u < UU; u += 1024) {
        g_topk[b * UP + u] = si[u];
        g_ulookup[b * LQ + si[u]] = u;
    }
}

// ---------------- denom: sum 16 exp-sum partials per (b,u) ----------------
__global__ void k_denom()
{
    int b = blockIdx.x, u = threadIdx.x;      // 512 threads
    const float* p = g_spart + ((size_t)b * UP + u) * 16;
    float s = 0.f;
    #pragma unroll
    for (int i = 0; i < 16; i++) s += p[i];
    g_denom[b * UP + u] = s;
}

// ---------------- vmean: sum 64 l-tile partials per (b,d) ----------------
__global__ void k_vmean2()
{
    int b = blockIdx.x, d = threadIdx.x;
    float acc = 0.f;
    #pragma unroll 8
    for (int t = 0; t < 64; t++)
        acc += g_vpart2[((size_t)b * 64 + t) * DD + d];
    g_vmean[b * DD + d] = acc * (1.0f / LQ);
}

// ---------------- fused output: vmean broadcast or (updA+updB)/denom ----------------
__global__ void k_output(float* __restrict__ out)
{
    int b = blockIdx.y, l = blockIdx.x, t = threadIdx.x;
    int u = g_ulookup[b * LQ + l];
    float4 r;
    if (u >= 0) {
        float inv = 1.f / g_denom[b * UP + u];
        float4 a = ((const float4*)(g_updA + ((size_t)b * UP + u) * DD))[t];
        float4 c = ((const float4*)(g_updB + ((size_t)b * UP + u) * DD))[t];
        r = make_float4((a.x + c.x) * inv, (a.y + c.y) * inv,
                        (a.z + c.z) * inv, (a.w + c.w) * inv);
    } else {
        r = ((const float4*)(g_vmean + (size_t)b * DD))[t];
    }
    ((float4*)(out + (size_t)b * PER_BATCH + (size_t)l * DD))[t] = r;
}

// ---------------- launch (single stream; graph-linear) ----------------
extern "C" void kernel_launch(void* const* d_in, const int* in_sizes, int n_in,
                              void* d_out, int out_size)
{
    const float* in1 = (const float*)d_in[0];
    const float* in2 = (const float*)d_in[1];
    const float* Wq  = (const float*)d_in[2];
    const float* bq  = (const float*)d_in[3];
    const float* Wk  = (const float*)d_in[4];
    const float* bk  = (const float*)d_in[5];
    const float* Wv  = (const float*)d_in[6];
    const float* bv  = (const float*)d_in[7];
    const int*   idx = (const int*)d_in[8];
    float* out = (float*)d_out;

    cudaFuncSetAttribute(k_proj,   cudaFuncAttributeMaxDynamicSharedMemorySize, SM_TOTAL);
    cudaFuncSetAttribute(k_qks,    cudaFuncAttributeMaxDynamicSharedMemorySize, SM_TOTAL);
    cudaFuncSetAttribute(k_scores, cudaFuncAttributeMaxDynamicSharedMemorySize, SM_TOTAL);
    cudaFuncSetAttribute(k_upd,    cudaFuncAttributeMaxDynamicSharedMemorySize, SM_TOTAL);

    k_convW<<<3072, 256>>>(Wq, Wk, Wv);
    k_convX<<<dim3(LQ / 32, CC / 32, NB), dim3(32, 8)>>>(in1, in2);

    // merged projections: Q, K, V in one launch (3072 CTAs)
    k_proj<<<dim3(LQ / 256, DD / 128, NB * 3), 256, SM_TOTAL>>>(bq, bk, bv);

    k_transV<<<dim3(DD / 32, LQ / 64, NB), dim3(32, 8)>>>();
    k_vmean2<<<NB, 512>>>();

    k_gather_ks<<<dim3(UP, NB), 128>>>(idx);
    k_qks<<<dim3(UP / 256, LQ / 128, NB), 256, SM_TOTAL>>>();
    k_topk<<<NB, 1024>>>();
    k_gather_qr<<<dim3(UP, NB), 128>>>();

    k_scores<<<dim3(LQ / 256, UP / 128, NB), 256, SM_TOTAL>>>();
    k_denom<<<NB, 512>>>();
    k_upd<<<dim3(DD / 256, UP / 128, NB * 2), 256, SM_TOTAL>>>();

    k_output<<<dim3(LQ, NB), 128>>>(out);
}